// round 1
// baseline (speedup 1.0000x reference)
#include <cuda_runtime.h>
#include <math.h>

#define NB 64
#define NC 64
#define NS 128
#define NH 512
#define ND (NS*NH)        // 65536
#define NSS (NS*NS)       // 16384
#define EPS_F 1e-8f

#define OUT_LOSS 0
#define OUT_DIST 1
#define OUT_CW   (1 + NB*NC)            // 4097
#define OUT_IDX  (OUT_CW + NC*ND)       // 4198401

// -------- device scratch (no allocations allowed) --------
__device__ float g_cg[(NB + NC) * NSS];   // centered grams: [0..63]=cgx, [64..127]=cgy (8 MB)
__device__ float g_h[NB + NC];            // hxx[0..63], hyy[64..127]
__device__ float g_sq[NB + NC];           // x2[0..63], w2[64..127]
__device__ float g_dot[NB * NC];          // X @ W^T
__device__ float g_P[64 * NB * NC];       // K-split partials for hxy / hxy2
__device__ float g_hxy[NB * NC];
__device__ float g_hxy2[NB * NB];
__device__ int   g_idxv[NB];

// =====================================================================
// Kernel 1: gram + centering + sum-of-squares.
// One block per matrix (128 blocks: 64 x-rows, 64 w-rows).
// SYRK of M (128x512): G = M M^T held in registers (8x8/thread), dumped to
// smem for centering (G symmetric => rowmean == colmean).
// =====================================================================
__global__ void gram_kernel(const float* __restrict__ x, const float* __restrict__ w) {
    extern __shared__ float sm[];          // reused: chunk buffer, then Gs
    const int m   = blockIdx.x;
    const float* M = (m < NB) ? (x + (size_t)m * ND) : (w + (size_t)(m - NB) * ND);
    const int tid = threadIdx.x;
    const int tx  = tid & 15;
    const int ty  = tid >> 4;

    float acc[8][8];
#pragma unroll
    for (int u = 0; u < 8; u++)
#pragma unroll
        for (int v = 0; v < 8; v++) acc[u][v] = 0.0f;

    // K loop over H=512 in chunks of 32, chunk stored transposed: Ms[kk*133 + r]
    float* Ms = sm;
    for (int k0 = 0; k0 < NH; k0 += 32) {
        __syncthreads();
        for (int i = tid; i < 1024; i += 256) {       // 128 rows x 8 float4
            int r  = i >> 3;
            int c4 = (i & 7) * 4;
            float4 v = *(const float4*)(M + (size_t)r * NH + k0 + c4);
            Ms[(c4 + 0) * 133 + r] = v.x;
            Ms[(c4 + 1) * 133 + r] = v.y;
            Ms[(c4 + 2) * 133 + r] = v.z;
            Ms[(c4 + 3) * 133 + r] = v.w;
        }
        __syncthreads();
#pragma unroll 8
        for (int kk = 0; kk < 32; kk++) {
            float a[8], b[8];
#pragma unroll
            for (int u = 0; u < 8; u++) a[u] = Ms[kk * 133 + ty + 16 * u];
#pragma unroll
            for (int v = 0; v < 8; v++) b[v] = Ms[kk * 133 + tx + 16 * v];
#pragma unroll
            for (int u = 0; u < 8; u++)
#pragma unroll
                for (int v = 0; v < 8; v++) acc[u][v] += a[u] * b[v];
        }
    }
    __syncthreads();

    // Dump G to smem (stride 129 => conflict-free row sums)
    float* Gs = sm;                 // [128][129]
    float* rs = sm + 128 * 129;     // row sums + grand mean
#pragma unroll
    for (int u = 0; u < 8; u++)
#pragma unroll
        for (int v = 0; v < 8; v++)
            Gs[(ty + 16 * u) * 129 + (tx + 16 * v)] = acc[u][v];
    __syncthreads();

    if (tid < 128) {
        float s = 0.0f;
        const float* row = Gs + tid * 129;
        for (int j = 0; j < 128; j++) s += row[j];
        rs[tid] = s;
    }
    __syncthreads();
    if (tid == 0) {
        float g = 0.0f;
        for (int j = 0; j < 128; j++) g += rs[j];
        rs[128] = g / (128.0f * 128.0f);
    }
    __syncthreads();

    const float gm = rs[128];
    float* outg = g_cg + (size_t)m * NSS;
    float ss = 0.0f;
    for (int t = tid; t < NSS; t += 256) {
        int i = t >> 7, j = t & 127;
        float v = Gs[i * 129 + j] - rs[i] * (1.0f / 128.0f) - rs[j] * (1.0f / 128.0f) + gm;
        outg[t] = v;
        ss += v * v;
    }
    __shared__ float red[256];
    red[tid] = ss;
    __syncthreads();
    for (int s = 128; s > 0; s >>= 1) {
        if (tid < s) red[tid] += red[tid + s];
        __syncthreads();
    }
    if (tid == 0) g_h[m] = red[0];
}

// =====================================================================
// Kernel 2: row squared norms (x2 / w2)
// =====================================================================
__global__ void norms_kernel(const float* __restrict__ x, const float* __restrict__ w) {
    const int m = blockIdx.x;
    const float* M = (m < NB) ? (x + (size_t)m * ND) : (w + (size_t)(m - NB) * ND);
    float s = 0.0f;
    for (int i = threadIdx.x * 4; i < ND; i += 256 * 4) {
        float4 v = *(const float4*)(M + i);
        s += v.x * v.x + v.y * v.y + v.z * v.z + v.w * v.w;
    }
    __shared__ float red[256];
    red[threadIdx.x] = s;
    __syncthreads();
    for (int st = 128; st > 0; st >>= 1) {
        if (threadIdx.x < st) red[threadIdx.x] += red[threadIdx.x + st];
        __syncthreads();
    }
    if (threadIdx.x == 0) g_sq[m] = red[0];
}

// =====================================================================
// Kernel 3: zero the dist-dot accumulator (graph replays need fresh zeros)
// =====================================================================
__global__ void zero_dot_kernel() {
    g_dot[blockIdx.x * 256 + threadIdx.x] = 0.0f;
}

// =====================================================================
// Kernel 4: X @ W^T partials, K split across 128 blocks (512 cols each),
// fp32 atomicAdd accumulation (dist is tolerance-checked, not argmax'd).
// =====================================================================
__global__ void dist_partial_kernel(const float* __restrict__ x, const float* __restrict__ w) {
    __shared__ float Xs[32 * 69];
    __shared__ float Ws[32 * 69];
    const int tid = threadIdx.x;
    const int tx  = tid & 15;
    const int ty  = tid >> 4;
    const int kbase = blockIdx.x * 512;

    float acc[4][4];
#pragma unroll
    for (int u = 0; u < 4; u++)
#pragma unroll
        for (int v = 0; v < 4; v++) acc[u][v] = 0.0f;

    for (int k0 = 0; k0 < 512; k0 += 32) {
        __syncthreads();
        for (int i = tid; i < 512; i += 256) {      // 64 rows x 8 float4
            int r  = i >> 3;
            int c4 = (i & 7) * 4;
            float4 vx = *(const float4*)(x + (size_t)r * ND + kbase + k0 + c4);
            float4 vw = *(const float4*)(w + (size_t)r * ND + kbase + k0 + c4);
            Xs[(c4 + 0) * 69 + r] = vx.x; Xs[(c4 + 1) * 69 + r] = vx.y;
            Xs[(c4 + 2) * 69 + r] = vx.z; Xs[(c4 + 3) * 69 + r] = vx.w;
            Ws[(c4 + 0) * 69 + r] = vw.x; Ws[(c4 + 1) * 69 + r] = vw.y;
            Ws[(c4 + 2) * 69 + r] = vw.z; Ws[(c4 + 3) * 69 + r] = vw.w;
        }
        __syncthreads();
#pragma unroll 8
        for (int kk = 0; kk < 32; kk++) {
            float a[4], b[4];
#pragma unroll
            for (int u = 0; u < 4; u++) a[u] = Xs[kk * 69 + ty + 16 * u];
#pragma unroll
            for (int v = 0; v < 4; v++) b[v] = Ws[kk * 69 + tx + 16 * v];
#pragma unroll
            for (int u = 0; u < 4; u++)
#pragma unroll
                for (int v = 0; v < 4; v++) acc[u][v] += a[u] * b[v];
        }
    }
#pragma unroll
    for (int u = 0; u < 4; u++)
#pragma unroll
        for (int v = 0; v < 4; v++)
            atomicAdd(&g_dot[(ty + 16 * u) * NC + (tx + 16 * v)], acc[u][v]);
}

// =====================================================================
// Kernel 5: finalize dist = sqrt(max(x2 + w2 - 2 dot, 0))
// =====================================================================
__global__ void dist_final_kernel(float* __restrict__ out) {
    int t = blockIdx.x * 256 + threadIdx.x;     // 4096
    int b = t >> 6, c = t & 63;
    float d2 = g_sq[b] + g_sq[NB + c] - 2.0f * g_dot[t];
    out[OUT_DIST + t] = sqrtf(fmaxf(d2, 0.0f));
}

// =====================================================================
// Kernel 6: hxy / hxy2 partials. 64 blocks, each owns a 256-wide K slice of
// the 16384-dim flattened gram dot. Deterministic: partials + ordered reduce
// (this feeds argmax -> idx must be stable).
// use_idx=0: B-rows = cgy[c];  use_idx=1: B-rows = cgy[g_idxv[c]]
// =====================================================================
__global__ void hsic_partial_kernel(int use_idx) {
    __shared__ float As[32 * 69];
    __shared__ float Bs[32 * 69];
    __shared__ int   sidx[64];
    const int tid = threadIdx.x;
    const int tx  = tid & 15;
    const int ty  = tid >> 4;
    if (tid < 64) sidx[tid] = use_idx ? g_idxv[tid] : tid;
    __syncthreads();
    const int kbase = blockIdx.x * 256;

    float acc[4][4];
#pragma unroll
    for (int u = 0; u < 4; u++)
#pragma unroll
        for (int v = 0; v < 4; v++) acc[u][v] = 0.0f;

    for (int k0 = 0; k0 < 256; k0 += 32) {
        __syncthreads();
        for (int i = tid; i < 512; i += 256) {
            int r  = i >> 3;
            int c4 = (i & 7) * 4;
            const float* arow = g_cg + (size_t)r * NSS;
            const float* brow = g_cg + (size_t)(NB + sidx[r]) * NSS;
            float4 va = *(const float4*)(arow + kbase + k0 + c4);
            float4 vb = *(const float4*)(brow + kbase + k0 + c4);
            As[(c4 + 0) * 69 + r] = va.x; As[(c4 + 1) * 69 + r] = va.y;
            As[(c4 + 2) * 69 + r] = va.z; As[(c4 + 3) * 69 + r] = va.w;
            Bs[(c4 + 0) * 69 + r] = vb.x; Bs[(c4 + 1) * 69 + r] = vb.y;
            Bs[(c4 + 2) * 69 + r] = vb.z; Bs[(c4 + 3) * 69 + r] = vb.w;
        }
        __syncthreads();
#pragma unroll 8
        for (int kk = 0; kk < 32; kk++) {
            float a[4], b[4];
#pragma unroll
            for (int u = 0; u < 4; u++) a[u] = As[kk * 69 + ty + 16 * u];
#pragma unroll
            for (int v = 0; v < 4; v++) b[v] = Bs[kk * 69 + tx + 16 * v];
#pragma unroll
            for (int u = 0; u < 4; u++)
#pragma unroll
                for (int v = 0; v < 4; v++) acc[u][v] += a[u] * b[v];
        }
    }
    float* P = g_P + (size_t)blockIdx.x * (NB * NC);
#pragma unroll
    for (int u = 0; u < 4; u++)
#pragma unroll
        for (int v = 0; v < 4; v++)
            P[(ty + 16 * u) * NC + (tx + 16 * v)] = acc[u][v];
}

// =====================================================================
// Kernel 7: deterministic reduce of the 64 K-slice partials
// =====================================================================
__global__ void reduce_partials_kernel(int which) {
    int t = blockIdx.x * 256 + threadIdx.x;     // 4096
    float s = 0.0f;
#pragma unroll 8
    for (int sl = 0; sl < 64; sl++) s += g_P[(size_t)sl * (NB * NC) + t];
    if (which) g_hxy2[t] = s;
    else       g_hxy[t]  = s;
}

// =====================================================================
// Kernel 8: cka_mat argmax (first-max tie-break, matching jnp.argmax)
// =====================================================================
__global__ void argmax_kernel(float* __restrict__ out) {
    int b = threadIdx.x;                 // 64 threads, 1 block
    if (b >= NB) return;
    float sx = sqrtf(g_h[b]);
    float best = -1e38f;
    int bi = 0;
    for (int c = 0; c < NC; c++) {
        float r = fabsf(g_hxy[b * NC + c]) / (sx * sqrtf(g_h[NB + c]));
        float cka = -logf(r + EPS_F);
        if (cka > best) { best = cka; bi = c; }
    }
    g_idxv[b] = bi;
    out[OUT_IDX + b] = (float)bi;
}

// =====================================================================
// Kernel 9: final loss = -log(mean(ratio) + eps)
// =====================================================================
__global__ void loss_kernel(float* __restrict__ out) {
    __shared__ float red[256];
    int tid = threadIdx.x;
    float s = 0.0f;
    for (int t = tid; t < NB * NB; t += 256) {
        int b = t >> 6, c = t & 63;
        float ratio = fabsf(g_hxy2[t]) / (sqrtf(g_h[b]) * sqrtf(g_h[NB + g_idxv[c]]));
        s += ratio;
    }
    red[tid] = s;
    __syncthreads();
    for (int st = 128; st > 0; st >>= 1) {
        if (tid < st) red[tid] += red[tid + st];
        __syncthreads();
    }
    if (tid == 0) out[OUT_LOSS] = -logf(red[0] / (float)(NB * NB) + EPS_F);
}

// =====================================================================
// host launch
// =====================================================================
extern "C" void kernel_launch(void* const* d_in, const int* in_sizes, int n_in,
                              void* d_out, int out_size) {
    const float* x = (const float*)d_in[0];          // input (64, 65536)
    const float* w = (const float*)d_in[1];          // centroid_weight (64, 65536)
    float* out = (float*)d_out;

    const int gram_smem = (128 * 129 + 129) * sizeof(float);   // 66564 B (> 48KB)
    cudaFuncSetAttribute(gram_kernel, cudaFuncAttributeMaxDynamicSharedMemorySize, gram_smem);

    gram_kernel<<<NB + NC, 256, gram_smem>>>(x, w);
    norms_kernel<<<NB + NC, 256>>>(x, w);
    zero_dot_kernel<<<16, 256>>>();
    dist_partial_kernel<<<128, 256>>>(x, w);
    dist_final_kernel<<<16, 256>>>(out);

    hsic_partial_kernel<<<64, 256>>>(0);
    reduce_partials_kernel<<<16, 256>>>(0);
    argmax_kernel<<<1, 64>>>(out);

    hsic_partial_kernel<<<64, 256>>>(1);
    reduce_partials_kernel<<<16, 256>>>(1);
    loss_kernel<<<1, 256>>>(out);

    // centroid_weight passthrough
    cudaMemcpyAsync(out + OUT_CW, w, (size_t)(NC) * ND * sizeof(float),
                    cudaMemcpyDeviceToDevice);
}

// round 3
// speedup vs baseline: 1.2996x; 1.2996x over previous
#include <cuda_runtime.h>
#include <math.h>

#define NB 64
#define NC 64
#define NS 128
#define NH 512
#define ND (NS*NH)        // 65536
#define NSS (NS*NS)       // 16384
#define EPS_F 1e-8f

#define OUT_LOSS 0
#define OUT_DIST 1
#define OUT_CW   (1 + NB*NC)            // 4097
#define OUT_IDX  (OUT_CW + NC*ND)       // 4198401

#define DIST_SLICES 512                 // K-split for X@W^T  (K=128 each)
#define HSIC_SLICES 128                 // K-split for gram dots (K=128 each)

// -------- device scratch (no allocations allowed) --------
__device__ float g_cg[(NB + NC) * NSS];       // centered grams (8 MB)
__device__ float g_h[NB + NC];                // hxx / hyy
__device__ float g_sq[NB + NC];               // x2 / w2 (via trace of gram)
__device__ float g_Pd[DIST_SLICES * NB * NC]; // dist K-slice partials (8 MB)
__device__ float g_P[HSIC_SLICES * NB * NC];  // hsic K-slice partials (2 MB)
__device__ float g_hxy2[NB * NB];
__device__ int   g_idxv[NB];

// =====================================================================
// PHASE 1 (single launch, role by blockIdx):
//   blocks [0,128)    : gram + centering + hxx/hyy + trace (symmetric SYRK)
//   blocks [128,640)  : dist partials, K-slice 128 per block
//   blocks [640,704)  : centroid passthrough copy (65536 floats each)
// =====================================================================

__device__ __forceinline__ void gram_body(int m, const float* __restrict__ x,
                                          const float* __restrict__ w, float* sm) {
    const float* M = (m < NB) ? (x + (size_t)m * ND) : (w + (size_t)(m - NB) * ND);
    const int tid = threadIdx.x;
    const int tx  = tid & 15;
    const int ty  = tid >> 4;

    // symmetric SYRK: C1 = full 128 rows x cols [0,64); C2 = block [64,128)^2
    float c1[8][4], c2[4][4];
#pragma unroll
    for (int u = 0; u < 8; u++)
#pragma unroll
        for (int v = 0; v < 4; v++) c1[u][v] = 0.0f;
#pragma unroll
    for (int u = 0; u < 4; u++)
#pragma unroll
        for (int v = 0; v < 4; v++) c2[u][v] = 0.0f;

    float* Ms = sm;                          // chunk transposed: [32][133]
    for (int k0 = 0; k0 < NH; k0 += 32) {
        __syncthreads();
        for (int i = tid; i < 1024; i += 256) {      // 128 rows x 8 float4
            int r  = i >> 3;
            int c4 = (i & 7) * 4;
            float4 v = *(const float4*)(M + (size_t)r * NH + k0 + c4);
            Ms[(c4 + 0) * 133 + r] = v.x;
            Ms[(c4 + 1) * 133 + r] = v.y;
            Ms[(c4 + 2) * 133 + r] = v.z;
            Ms[(c4 + 3) * 133 + r] = v.w;
        }
        __syncthreads();
#pragma unroll 8
        for (int kk = 0; kk < 32; kk++) {
            float a[8], b[8];
#pragma unroll
            for (int u = 0; u < 8; u++) a[u] = Ms[kk * 133 + ty + 16 * u];
#pragma unroll
            for (int v = 0; v < 8; v++) b[v] = Ms[kk * 133 + tx + 16 * v];
#pragma unroll
            for (int u = 0; u < 8; u++)
#pragma unroll
                for (int v = 0; v < 4; v++) c1[u][v] += a[u] * b[v];
#pragma unroll
            for (int u = 0; u < 4; u++)
#pragma unroll
                for (int v = 0; v < 4; v++) c2[u][v] += a[4 + u] * b[4 + v];
        }
    }
    __syncthreads();

    // Assemble full symmetric G in smem [128][129]
    float* Gs = sm;
    float* rs = sm + 128 * 129;              // row sums + grand mean
#pragma unroll
    for (int u = 0; u < 8; u++)
#pragma unroll
        for (int v = 0; v < 4; v++)
            Gs[(ty + 16 * u) * 129 + (tx + 16 * v)] = c1[u][v];
#pragma unroll
    for (int u = 4; u < 8; u++)              // mirror lower-left -> upper-right
#pragma unroll
        for (int v = 0; v < 4; v++)
            Gs[(tx + 16 * v) * 129 + (ty + 16 * u)] = c1[u][v];
#pragma unroll
    for (int u = 0; u < 4; u++)
#pragma unroll
        for (int v = 0; v < 4; v++)
            Gs[(64 + ty + 16 * u) * 129 + (64 + tx + 16 * v)] = c2[u][v];
    __syncthreads();

    __shared__ float red[256];
    // trace -> squared row norm
    red[tid] = (tid < 128) ? Gs[tid * 129 + tid] : 0.0f;
    // row sums
    if (tid < 128) {
        float s = 0.0f;
        const float* row = Gs + tid * 129;
        for (int j = 0; j < 128; j++) s += row[j];
        rs[tid] = s;
    }
    __syncthreads();
    if (tid == 0) {
        float g = 0.0f;
        for (int j = 0; j < 128; j++) g += rs[j];
        rs[128] = g / (128.0f * 128.0f);
    }
    for (int s = 128; s > 0; s >>= 1) {
        __syncthreads();
        if (tid < s) red[tid] += red[tid + s];
    }
    if (tid == 0) g_sq[m] = red[0];
    __syncthreads();

    const float gm = rs[128];
    float* outg = g_cg + (size_t)m * NSS;
    float ss = 0.0f;
    for (int t = tid; t < NSS; t += 256) {
        int i = t >> 7, j = t & 127;
        float v = Gs[i * 129 + j] - rs[i] * (1.0f / 128.0f) - rs[j] * (1.0f / 128.0f) + gm;
        outg[t] = v;
        ss += v * v;
    }
    __syncthreads();
    red[tid] = ss;
    for (int s = 128; s > 0; s >>= 1) {
        __syncthreads();
        if (tid < s) red[tid] += red[tid + s];
    }
    if (tid == 0) g_h[m] = red[0];
}

__device__ __forceinline__ void dist_body(int sl, const float* __restrict__ x,
                                          const float* __restrict__ w, float* sm) {
    float* Xs = sm;                 // [32][69]
    float* Ws = sm + 32 * 69;
    const int tid = threadIdx.x;
    const int tx  = tid & 15;
    const int ty  = tid >> 4;
    const int kbase = sl * 128;

    float acc[4][4];
#pragma unroll
    for (int u = 0; u < 4; u++)
#pragma unroll
        for (int v = 0; v < 4; v++) acc[u][v] = 0.0f;

    for (int k0 = 0; k0 < 128; k0 += 32) {
        __syncthreads();
        for (int i = tid; i < 512; i += 256) {       // 64 rows x 8 float4
            int r  = i >> 3;
            int c4 = (i & 7) * 4;
            float4 vx = *(const float4*)(x + (size_t)r * ND + kbase + k0 + c4);
            float4 vw = *(const float4*)(w + (size_t)r * ND + kbase + k0 + c4);
            Xs[(c4 + 0) * 69 + r] = vx.x; Xs[(c4 + 1) * 69 + r] = vx.y;
            Xs[(c4 + 2) * 69 + r] = vx.z; Xs[(c4 + 3) * 69 + r] = vx.w;
            Ws[(c4 + 0) * 69 + r] = vw.x; Ws[(c4 + 1) * 69 + r] = vw.y;
            Ws[(c4 + 2) * 69 + r] = vw.z; Ws[(c4 + 3) * 69 + r] = vw.w;
        }
        __syncthreads();
#pragma unroll 8
        for (int kk = 0; kk < 32; kk++) {
            float a[4], b[4];
#pragma unroll
            for (int u = 0; u < 4; u++) a[u] = Xs[kk * 69 + ty + 16 * u];
#pragma unroll
            for (int v = 0; v < 4; v++) b[v] = Ws[kk * 69 + tx + 16 * v];
#pragma unroll
            for (int u = 0; u < 4; u++)
#pragma unroll
                for (int v = 0; v < 4; v++) acc[u][v] += a[u] * b[v];
        }
    }
    float* P = g_Pd + (size_t)sl * (NB * NC);
#pragma unroll
    for (int u = 0; u < 4; u++)
#pragma unroll
        for (int v = 0; v < 4; v++)
            P[(ty + 16 * u) * NC + (tx + 16 * v)] = acc[u][v];
}

__device__ __forceinline__ void copy_body(int cb, const float* __restrict__ w,
                                          float* __restrict__ out) {
    // total NC*ND = 4,194,304 floats over 64 blocks => 65,536 floats/block
    // = 16,384 float4 loads. out+OUT_CW is only 4B aligned -> scalar stores.
    const float4* src = (const float4*)(w + (size_t)cb * 65536);
    float* dst = out + OUT_CW + (size_t)cb * 65536;
    const int tid = threadIdx.x;
    for (int i = tid; i < 16384; i += 256) {
        float4 v = __ldg(src + i);
        dst[i * 4 + 0] = v.x;
        dst[i * 4 + 1] = v.y;
        dst[i * 4 + 2] = v.z;
        dst[i * 4 + 3] = v.w;
    }
}

__global__ __launch_bounds__(256) void phase1_kernel(const float* __restrict__ x,
                                                     const float* __restrict__ w,
                                                     float* __restrict__ out) {
    extern __shared__ float sm[];
    const int bid = blockIdx.x;
    if (bid < 128)       gram_body(bid, x, w, sm);
    else if (bid < 640)  dist_body(bid - 128, x, w, sm);
    else                 copy_body(bid - 640, w, out);
}

// =====================================================================
// HSIC partial body: 64x64 tile, K-slice 128 of the flattened 16384 dim.
// =====================================================================
__device__ __forceinline__ void hsic_body(int sl, int use_idx, float* sm) {
    float* As = sm;
    float* Bs = sm + 32 * 69;
    __shared__ int sidx[64];
    const int tid = threadIdx.x;
    const int tx  = tid & 15;
    const int ty  = tid >> 4;
    if (tid < 64) sidx[tid] = use_idx ? g_idxv[tid] : tid;
    __syncthreads();
    const int kbase = sl * 128;

    float acc[4][4];
#pragma unroll
    for (int u = 0; u < 4; u++)
#pragma unroll
        for (int v = 0; v < 4; v++) acc[u][v] = 0.0f;

    for (int k0 = 0; k0 < 128; k0 += 32) {
        __syncthreads();
        for (int i = tid; i < 512; i += 256) {
            int r  = i >> 3;
            int c4 = (i & 7) * 4;
            const float* arow = g_cg + (size_t)r * NSS;
            const float* brow = g_cg + (size_t)(NB + sidx[r]) * NSS;
            float4 va = *(const float4*)(arow + kbase + k0 + c4);
            float4 vb = *(const float4*)(brow + kbase + k0 + c4);
            As[(c4 + 0) * 69 + r] = va.x; As[(c4 + 1) * 69 + r] = va.y;
            As[(c4 + 2) * 69 + r] = va.z; As[(c4 + 3) * 69 + r] = va.w;
            Bs[(c4 + 0) * 69 + r] = vb.x; Bs[(c4 + 1) * 69 + r] = vb.y;
            Bs[(c4 + 2) * 69 + r] = vb.z; Bs[(c4 + 3) * 69 + r] = vb.w;
        }
        __syncthreads();
#pragma unroll 8
        for (int kk = 0; kk < 32; kk++) {
            float a[4], b[4];
#pragma unroll
            for (int u = 0; u < 4; u++) a[u] = As[kk * 69 + ty + 16 * u];
#pragma unroll
            for (int v = 0; v < 4; v++) b[v] = Bs[kk * 69 + tx + 16 * v];
#pragma unroll
            for (int u = 0; u < 4; u++)
#pragma unroll
                for (int v = 0; v < 4; v++) acc[u][v] += a[u] * b[v];
        }
    }
    float* P = g_P + (size_t)sl * (NB * NC);
#pragma unroll
    for (int u = 0; u < 4; u++)
#pragma unroll
        for (int v = 0; v < 4; v++)
            P[(ty + 16 * u) * NC + (tx + 16 * v)] = acc[u][v];
}

// =====================================================================
// PHASE 2: hsic0 partials (blocks 0..127) + dist finalize (blocks 128..143)
// =====================================================================
__global__ __launch_bounds__(256) void phase2_kernel(float* __restrict__ out) {
    __shared__ float sm[2 * 32 * 69];
    const int bid = blockIdx.x;
    if (bid < HSIC_SLICES) {
        hsic_body(bid, 0, sm);
    } else {
        int t = (bid - HSIC_SLICES) * 256 + threadIdx.x;   // 0..4095
        float s = 0.0f;
        for (int sl = 0; sl < DIST_SLICES; sl++) s += g_Pd[(size_t)sl * (NB * NC) + t];
        int b = t >> 6, c = t & 63;
        float d2 = g_sq[b] + g_sq[NB + c] - 2.0f * s;
        out[OUT_DIST + t] = sqrtf(fmaxf(d2, 0.0f));
    }
}

// =====================================================================
// PHASE 3: reduce hsic0 partials per row + cka + argmax (64 blocks)
// =====================================================================
__global__ __launch_bounds__(256) void phase3_kernel(float* __restrict__ out) {
    __shared__ float red[256];
    __shared__ float scka[64];
    const int b   = blockIdx.x;
    const int tid = threadIdx.x;
    const int c    = tid & 63;
    const int part = tid >> 6;                 // 4 parts x 32 slices
    float s = 0.0f;
    for (int sl = part * 32; sl < part * 32 + 32; sl++)
        s += g_P[(size_t)sl * (NB * NC) + b * 64 + c];
    red[tid] = s;
    __syncthreads();
    if (tid < 64) {
        float h = red[c] + red[64 + c] + red[128 + c] + red[192 + c];
        float r = fabsf(h) / (sqrtf(g_h[b]) * sqrtf(g_h[NB + c]));
        scka[c] = -logf(r + EPS_F);
    }
    __syncthreads();
    if (tid == 0) {
        float best = scka[0];
        int bi = 0;
        for (int cc = 1; cc < 64; cc++)
            if (scka[cc] > best) { best = scka[cc]; bi = cc; }
        g_idxv[b] = bi;
        out[OUT_IDX + b] = (float)bi;
    }
}

// =====================================================================
// PHASE 4: hsic1 partials (gathered centroids)
// =====================================================================
__global__ __launch_bounds__(256) void phase4_kernel() {
    __shared__ float sm[2 * 32 * 69];
    hsic_body(blockIdx.x, 1, sm);
}

// =====================================================================
// PHASE 5a: reduce hsic1 partials -> g_hxy2
// =====================================================================
__global__ __launch_bounds__(256) void phase5a_kernel() {
    int t = blockIdx.x * 256 + threadIdx.x;
    float s = 0.0f;
#pragma unroll 8
    for (int sl = 0; sl < HSIC_SLICES; sl++) s += g_P[(size_t)sl * (NB * NC) + t];
    g_hxy2[t] = s;
}

// =====================================================================
// PHASE 5b: final loss
// =====================================================================
__global__ __launch_bounds__(256) void phase5b_kernel(float* __restrict__ out) {
    __shared__ float red[256];
    int tid = threadIdx.x;
    float s = 0.0f;
    for (int t = tid; t < NB * NB; t += 256) {
        int b = t >> 6, c = t & 63;
        float ratio = fabsf(g_hxy2[t]) / (sqrtf(g_h[b]) * sqrtf(g_h[NB + g_idxv[c]]));
        s += ratio;
    }
    red[tid] = s;
    for (int st = 128; st > 0; st >>= 1) {
        __syncthreads();
        if (tid < st) red[tid] += red[tid + st];
    }
    if (tid == 0) out[OUT_LOSS] = -logf(red[0] / (float)(NB * NB) + EPS_F);
}

// =====================================================================
// host launch
// =====================================================================
extern "C" void kernel_launch(void* const* d_in, const int* in_sizes, int n_in,
                              void* d_out, int out_size) {
    const float* x = (const float*)d_in[0];
    const float* w = (const float*)d_in[1];
    float* out = (float*)d_out;

    const int smem1 = (128 * 129 + 129) * sizeof(float);   // 66564 B
    cudaFuncSetAttribute(phase1_kernel, cudaFuncAttributeMaxDynamicSharedMemorySize, smem1);

    phase1_kernel<<<704, 256, smem1>>>(x, w, out);
    phase2_kernel<<<HSIC_SLICES + 16, 256>>>(out);
    phase3_kernel<<<64, 256>>>(out);
    phase4_kernel<<<HSIC_SLICES, 256>>>();
    phase5a_kernel<<<16, 256>>>();
    phase5b_kernel<<<1, 256>>>(out);
}

// round 5
// speedup vs baseline: 1.8073x; 1.3906x over previous
#include <cuda_runtime.h>
#include <cuda_bf16.h>
#include <math.h>
#include <stdint.h>

#define NB 64
#define NC 64
#define NS 128
#define NH 512
#define ND (NS*NH)        // 65536
#define NSS (NS*NS)       // 16384
#define EPS_F 1e-8f

#define OUT_LOSS 0
#define OUT_DIST 1
#define OUT_CW   (1 + NB*NC)            // 4097
#define OUT_IDX  (OUT_CW + NC*ND)       // 4198401

#define DIST_SLICES 128                 // K-split for X@W^T (K=512 each)
#define HSIC_SLICES 256                 // K-split for gram dots (K=64 each)
#define COPY_BLKS   32

// gram bf16 tile: 128 rows x 64 k, row stride 72 bf16 (=36 u32) for bank-conflict-free frags
#define TSTRIDE_U32 36
#define P1_SMEM_BYTES (128 * TSTRIDE_U32 * 2 * 4)   // hi + lo = 36864 B

// -------- device scratch (no allocations allowed) --------
__device__ __align__(16) float g_cg[(NB + NC) * NSS];   // centered grams (8 MB)
__device__ float g_h[NB + NC];                          // hxx / hyy
__device__ float g_sq[NB + NC];                         // x2 / w2 (trace of gram)
__device__ float g_Pd[DIST_SLICES * NB * NC];           // dist K-slice partials
__device__ float g_P[HSIC_SLICES * NB * NC];            // hsic K-slice partials
__device__ float g_hxy[NB * NC];
__device__ int   g_idxv[NB];

// ===================== warp-level bf16 MMA (sm_80+ baseline PTX) ============
__device__ __forceinline__ void mma16816(float* c, const uint32_t* a,
                                         uint32_t b0, uint32_t b1) {
    asm volatile(
        "mma.sync.aligned.m16n8k16.row.col.f32.bf16.bf16.f32 "
        "{%0,%1,%2,%3}, {%4,%5,%6,%7}, {%8,%9}, {%0,%1,%2,%3};"
        : "+f"(c[0]), "+f"(c[1]), "+f"(c[2]), "+f"(c[3])
        : "r"(a[0]), "r"(a[1]), "r"(a[2]), "r"(a[3]), "r"(b0), "r"(b1));
}
__device__ __forceinline__ uint32_t pk(__nv_bfloat16 a, __nv_bfloat16 b) {
    __nv_bfloat162 t = __halves2bfloat162(a, b);
    return *(uint32_t*)&t;
}

// =====================================================================
// gram via mma.sync: G = hi.hi^T + hi.lo^T + lo.hi^T (bf16 split of fp32 M)
// block = 256 thr = 8 warps. warp w: rows (w&3)*32 (two m16 tiles),
// cols (w>>2)*64 (eight n8 tiles). Accumulators in registers.
// =====================================================================
__device__ void gram_body(int m, const float* __restrict__ x,
                          const float* __restrict__ w, float* sm) {
    const float* Mp = (m < NB) ? (x + (size_t)m * ND) : (w + (size_t)(m - NB) * ND);
    const int tid  = threadIdx.x;
    const int wid  = tid >> 5;
    const int lane = tid & 31;
    const int g    = lane >> 2;
    const int tig  = lane & 3;
    const int rbase = (wid & 3) * 32;
    const int cbase = (wid >> 2) * 64;

    uint32_t* hiU = (uint32_t*)sm;               // [128][36]
    uint32_t* loU = hiU + 128 * TSTRIDE_U32;

    __shared__ float rs_part[2][128];
    __shared__ float rs[130];
    __shared__ float red[256];

    float c[2][8][4];
#pragma unroll
    for (int rt = 0; rt < 2; rt++)
#pragma unroll
        for (int nt = 0; nt < 8; nt++)
#pragma unroll
            for (int e = 0; e < 4; e++) c[rt][nt][e] = 0.0f;

    for (int ch = 0; ch < 8; ch++) {
        __syncthreads();
        const float* src = Mp + ch * 64;
        for (int i = tid; i < 2048; i += 256) {      // 128 rows x 16 float4
            int r  = i >> 4;
            int c4 = (i & 15) << 2;
            float4 v = *(const float4*)(src + (size_t)r * NH + c4);
            __nv_bfloat16 h0 = __float2bfloat16(v.x);
            __nv_bfloat16 h1 = __float2bfloat16(v.y);
            __nv_bfloat16 h2 = __float2bfloat16(v.z);
            __nv_bfloat16 h3 = __float2bfloat16(v.w);
            __nv_bfloat16 l0 = __float2bfloat16(v.x - __bfloat162float(h0));
            __nv_bfloat16 l1 = __float2bfloat16(v.y - __bfloat162float(h1));
            __nv_bfloat16 l2 = __float2bfloat16(v.z - __bfloat162float(h2));
            __nv_bfloat16 l3 = __float2bfloat16(v.w - __bfloat162float(h3));
            int idx = r * TSTRIDE_U32 + (c4 >> 1);
            *(uint2*)(hiU + idx) = make_uint2(pk(h0, h1), pk(h2, h3));
            *(uint2*)(loU + idx) = make_uint2(pk(l0, l1), pk(l2, l3));
        }
        __syncthreads();
#pragma unroll
        for (int ks = 0; ks < 4; ks++) {
            const int kw = ks * 8;                   // k0/2 in u32 units
            uint32_t ah[2][4], al[2][4];
#pragma unroll
            for (int rt = 0; rt < 2; rt++) {
                int r0 = rbase + rt * 16 + g;
                int w0 = r0 * TSTRIDE_U32 + kw + tig;
                ah[rt][0] = hiU[w0];
                ah[rt][1] = hiU[w0 + 8 * TSTRIDE_U32];
                ah[rt][2] = hiU[w0 + 4];
                ah[rt][3] = hiU[w0 + 8 * TSTRIDE_U32 + 4];
                al[rt][0] = loU[w0];
                al[rt][1] = loU[w0 + 8 * TSTRIDE_U32];
                al[rt][2] = loU[w0 + 4];
                al[rt][3] = loU[w0 + 8 * TSTRIDE_U32 + 4];
            }
#pragma unroll
            for (int nt = 0; nt < 8; nt++) {
                int nr = cbase + nt * 8 + g;
                int wb = nr * TSTRIDE_U32 + kw + tig;
                uint32_t bh0 = hiU[wb], bh1 = hiU[wb + 4];
                uint32_t bl0 = loU[wb], bl1 = loU[wb + 4];
#pragma unroll
                for (int rt = 0; rt < 2; rt++) {
                    mma16816(c[rt][nt], ah[rt], bh0, bh1);
                    mma16816(c[rt][nt], ah[rt], bl0, bl1);
                    mma16816(c[rt][nt], al[rt], bh0, bh1);
                }
            }
        }
    }

    // ---- row sums from fragments (col sums equal by symmetry) ----
#pragma unroll
    for (int rt = 0; rt < 2; rt++) {
        float s0 = 0.0f, s1 = 0.0f;
#pragma unroll
        for (int nt = 0; nt < 8; nt++) {
            s0 += c[rt][nt][0] + c[rt][nt][1];
            s1 += c[rt][nt][2] + c[rt][nt][3];
        }
        s0 += __shfl_xor_sync(0xFFFFFFFF, s0, 1);
        s0 += __shfl_xor_sync(0xFFFFFFFF, s0, 2);
        s1 += __shfl_xor_sync(0xFFFFFFFF, s1, 1);
        s1 += __shfl_xor_sync(0xFFFFFFFF, s1, 2);
        if (tig == 0) {
            rs_part[wid >> 2][rbase + rt * 16 + g]     = s0;
            rs_part[wid >> 2][rbase + rt * 16 + 8 + g] = s1;
        }
    }
    __syncthreads();
    if (tid < 128)
        rs[tid] = (rs_part[0][tid] + rs_part[1][tid]) * (1.0f / 128.0f);  // row means
    __syncthreads();
    if (tid == 0) {
        float gsum = 0.0f;
        for (int j = 0; j < 128; j++) gsum += rs[j];
        rs[128] = gsum * (1.0f / 128.0f);            // grand mean
    }

    // ---- trace (uncentered) -> g_sq ----
    float diag = 0.0f;
#pragma unroll
    for (int rt = 0; rt < 2; rt++)
#pragma unroll
        for (int h = 0; h < 2; h++) {
            int r = rbase + rt * 16 + h * 8 + g;
            if ((r >> 6) == (wid >> 2) && tig == ((r & 7) >> 1)) {
                int nt = (r & 63) >> 3;
                diag += c[rt][nt][h * 2 + (r & 1)];
            }
        }
    red[tid] = diag;
    for (int s = 128; s > 0; s >>= 1) {
        __syncthreads();
        if (tid < s) red[tid] += red[tid + s];
    }
    if (tid == 0) g_sq[m] = red[0];
    __syncthreads();

    // ---- center, hxx, store ----
    const float gm = rs[128];
    float* outg = g_cg + (size_t)m * NSS;
    float ss = 0.0f;
#pragma unroll
    for (int rt = 0; rt < 2; rt++) {
        int r0 = rbase + rt * 16 + g;
        int r1 = r0 + 8;
        float rm0 = rs[r0], rm1 = rs[r1];
#pragma unroll
        for (int nt = 0; nt < 8; nt++) {
            int cc = cbase + nt * 8 + tig * 2;
            float cm0 = rs[cc], cm1 = rs[cc + 1];
            float v0 = c[rt][nt][0] - rm0 - cm0 + gm;
            float v1 = c[rt][nt][1] - rm0 - cm1 + gm;
            float v2 = c[rt][nt][2] - rm1 - cm0 + gm;
            float v3 = c[rt][nt][3] - rm1 - cm1 + gm;
            ss += v0 * v0 + v1 * v1 + v2 * v2 + v3 * v3;
            *(float2*)(outg + r0 * 128 + cc) = make_float2(v0, v1);
            *(float2*)(outg + r1 * 128 + cc) = make_float2(v2, v3);
        }
    }
    __syncthreads();
    red[tid] = ss;
    for (int s = 128; s > 0; s >>= 1) {
        __syncthreads();
        if (tid < s) red[tid] += red[tid + s];
    }
    if (tid == 0) g_h[m] = red[0];
}

// =====================================================================
// dist partial: 64x64 tile, K-slice 512 (fp32 FFMA on the free fma pipe)
// =====================================================================
__device__ __forceinline__ void dist_body(int sl, const float* __restrict__ x,
                                          const float* __restrict__ w, float* sm) {
    float* Xs = sm;                 // [32][69]
    float* Ws = sm + 32 * 69;
    const int tid = threadIdx.x;
    const int tx  = tid & 15;
    const int ty  = tid >> 4;
    const int kbase = sl * 512;

    float acc[4][4];
#pragma unroll
    for (int u = 0; u < 4; u++)
#pragma unroll
        for (int v = 0; v < 4; v++) acc[u][v] = 0.0f;

    for (int k0 = 0; k0 < 512; k0 += 32) {
        __syncthreads();
        for (int i = tid; i < 512; i += 256) {       // 64 rows x 8 float4
            int r  = i >> 3;
            int c4 = (i & 7) * 4;
            float4 vx = *(const float4*)(x + (size_t)r * ND + kbase + k0 + c4);
            float4 vw = *(const float4*)(w + (size_t)r * ND + kbase + k0 + c4);
            Xs[(c4 + 0) * 69 + r] = vx.x; Xs[(c4 + 1) * 69 + r] = vx.y;
            Xs[(c4 + 2) * 69 + r] = vx.z; Xs[(c4 + 3) * 69 + r] = vx.w;
            Ws[(c4 + 0) * 69 + r] = vw.x; Ws[(c4 + 1) * 69 + r] = vw.y;
            Ws[(c4 + 2) * 69 + r] = vw.z; Ws[(c4 + 3) * 69 + r] = vw.w;
        }
        __syncthreads();
#pragma unroll 8
        for (int kk = 0; kk < 32; kk++) {
            float a[4], b[4];
#pragma unroll
            for (int u = 0; u < 4; u++) a[u] = Xs[kk * 69 + ty + 16 * u];
#pragma unroll
            for (int v = 0; v < 4; v++) b[v] = Ws[kk * 69 + tx + 16 * v];
#pragma unroll
            for (int u = 0; u < 4; u++)
#pragma unroll
                for (int v = 0; v < 4; v++) acc[u][v] += a[u] * b[v];
        }
    }
    float* P = g_Pd + (size_t)sl * (NB * NC);
#pragma unroll
    for (int u = 0; u < 4; u++)
#pragma unroll
        for (int v = 0; v < 4; v++)
            P[(ty + 16 * u) * NC + (tx + 16 * v)] = acc[u][v];
}

__device__ __forceinline__ void copy_body(int cb, const float* __restrict__ w,
                                          float* __restrict__ out) {
    // NC*ND = 4,194,304 floats over 32 blocks => 131072 floats = 32768 float4 / block
    const float4* src = (const float4*)(w + (size_t)cb * 131072);
    float* dst = out + OUT_CW + (size_t)cb * 131072;
    const int tid = threadIdx.x;
    for (int i = tid; i < 32768; i += 256) {
        float4 v = __ldg(src + i);
        dst[i * 4 + 0] = v.x;
        dst[i * 4 + 1] = v.y;
        dst[i * 4 + 2] = v.z;
        dst[i * 4 + 3] = v.w;
    }
}

__global__ __launch_bounds__(256) void phase1_kernel(const float* __restrict__ x,
                                                     const float* __restrict__ w,
                                                     float* __restrict__ out) {
    extern __shared__ float sm[];
    const int bid = blockIdx.x;
    if (bid < 128)              gram_body(bid, x, w, sm);
    else if (bid < 128 + COPY_BLKS) copy_body(bid - 128, w, out);
    else                        dist_body(bid - 128 - COPY_BLKS, x, w, sm);
}

// =====================================================================
// HSIC partial: 64x64 tile, K-slice 64 of the flattened 16384 dim
// =====================================================================
__device__ __forceinline__ void hsic_body(int sl, float* sm) {
    float* As = sm;
    float* Bs = sm + 32 * 69;
    const int tid = threadIdx.x;
    const int tx  = tid & 15;
    const int ty  = tid >> 4;
    const int kbase = sl * 64;

    float acc[4][4];
#pragma unroll
    for (int u = 0; u < 4; u++)
#pragma unroll
        for (int v = 0; v < 4; v++) acc[u][v] = 0.0f;

    for (int k0 = 0; k0 < 64; k0 += 32) {
        __syncthreads();
        for (int i = tid; i < 512; i += 256) {
            int r  = i >> 3;
            int c4 = (i & 7) * 4;
            const float* arow = g_cg + (size_t)r * NSS;
            const float* brow = g_cg + (size_t)(NB + r) * NSS;
            float4 va = *(const float4*)(arow + kbase + k0 + c4);
            float4 vb = *(const float4*)(brow + kbase + k0 + c4);
            As[(c4 + 0) * 69 + r] = va.x; As[(c4 + 1) * 69 + r] = va.y;
            As[(c4 + 2) * 69 + r] = va.z; As[(c4 + 3) * 69 + r] = va.w;
            Bs[(c4 + 0) * 69 + r] = vb.x; Bs[(c4 + 1) * 69 + r] = vb.y;
            Bs[(c4 + 2) * 69 + r] = vb.z; Bs[(c4 + 3) * 69 + r] = vb.w;
        }
        __syncthreads();
#pragma unroll 8
        for (int kk = 0; kk < 32; kk++) {
            float a[4], b[4];
#pragma unroll
            for (int u = 0; u < 4; u++) a[u] = As[kk * 69 + ty + 16 * u];
#pragma unroll
            for (int v = 0; v < 4; v++) b[v] = Bs[kk * 69 + tx + 16 * v];
#pragma unroll
            for (int u = 0; u < 4; u++)
#pragma unroll
                for (int v = 0; v < 4; v++) acc[u][v] += a[u] * b[v];
        }
    }
    float* P = g_P + (size_t)sl * (NB * NC);
#pragma unroll
    for (int u = 0; u < 4; u++)
#pragma unroll
        for (int v = 0; v < 4; v++)
            P[(ty + 16 * u) * NC + (tx + 16 * v)] = acc[u][v];
}

// =====================================================================
// PHASE 2: hsic partials (0..255) + dist finalize (256..271)
// =====================================================================
__global__ __launch_bounds__(256) void phase2_kernel(float* __restrict__ out) {
    __shared__ float sm[2 * 32 * 69];
    const int bid = blockIdx.x;
    if (bid < HSIC_SLICES) {
        hsic_body(bid, sm);
    } else {
        int t = (bid - HSIC_SLICES) * 256 + threadIdx.x;   // 0..4095
        float s = 0.0f;
        for (int sl = 0; sl < DIST_SLICES; sl++) s += g_Pd[(size_t)sl * (NB * NC) + t];
        int b = t >> 6, c = t & 63;
        float d2 = g_sq[b] + g_sq[NB + c] - 2.0f * s;
        out[OUT_DIST + t] = sqrtf(fmaxf(d2, 0.0f));
    }
}

// =====================================================================
// PHASE 3: reduce hsic partials -> g_hxy, argmax(cka) = argmin(ratio)
// =====================================================================
__global__ __launch_bounds__(256) void phase3_kernel(float* __restrict__ out) {
    __shared__ float red[256];
    __shared__ float sr[64];
    const int b   = blockIdx.x;
    const int tid = threadIdx.x;
    const int c    = tid & 63;
    const int part = tid >> 6;                 // 4 parts x 64 slices
    float s = 0.0f;
    for (int sl = part * 64; sl < part * 64 + 64; sl++)
        s += g_P[(size_t)sl * (NB * NC) + b * 64 + c];
    red[tid] = s;
    __syncthreads();
    if (tid < 64) {
        float h = red[c] + red[64 + c] + red[128 + c] + red[192 + c];
        g_hxy[b * 64 + c] = h;
        sr[c] = fabsf(h) / (sqrtf(g_h[b]) * sqrtf(g_h[NB + c]));
    }
    __syncthreads();
    if (tid == 0) {
        float best = sr[0];
        int bi = 0;
        for (int cc = 1; cc < 64; cc++)
            if (sr[cc] < best) { best = sr[cc]; bi = cc; }   // min ratio = max cka, first tie
        g_idxv[b] = bi;
        out[OUT_IDX + b] = (float)bi;
    }
}

// =====================================================================
// PHASE 4: loss by gather: hxy2[b][c] = hxy[b][idx[c]], hyy2[c] = hyy[idx[c]]
// =====================================================================
__global__ __launch_bounds__(256) void loss_kernel(float* __restrict__ out) {
    __shared__ float red[256];
    int tid = threadIdx.x;
    float s = 0.0f;
    for (int t = tid; t < NB * NB; t += 256) {
        int b = t >> 6, c = t & 63;
        int ic = g_idxv[c];
        float ratio = fabsf(g_hxy[b * 64 + ic]) /
                      (sqrtf(g_h[b]) * sqrtf(g_h[NB + ic]));
        s += ratio;
    }
    red[tid] = s;
    for (int st = 128; st > 0; st >>= 1) {
        __syncthreads();
        if (tid < st) red[tid] += red[tid + st];
    }
    if (tid == 0) out[OUT_LOSS] = -logf(red[0] / (float)(NB * NB) + EPS_F);
}

// =====================================================================
// host launch
// =====================================================================
extern "C" void kernel_launch(void* const* d_in, const int* in_sizes, int n_in,
                              void* d_out, int out_size) {
    const float* x = (const float*)d_in[0];
    const float* w = (const float*)d_in[1];
    float* out = (float*)d_out;

    phase1_kernel<<<128 + COPY_BLKS + DIST_SLICES, 256, P1_SMEM_BYTES>>>(x, w, out);
    phase2_kernel<<<HSIC_SLICES + 16, 256>>>(out);
    phase3_kernel<<<64, 256>>>(out);
    loss_kernel<<<1, 256>>>(out);
}